// round 14
// baseline (speedup 1.0000x reference)
#include <cuda_runtime.h>
#include <cuda_fp16.h>
#include <cstdint>

#define DK 4096
#define DN 4096
#define DM 8192
#define GROUP 128
#define EPSQ 1e-8f

#define BM 128
#define BN 128
#define BKE 128                // K elements per stage (two 64-col SW128 sub-tiles)
#define NSTAGES (DK / BKE)     // 32
#define NBUF 2

// ---------------- device scratch (allocation-free rule) ----------------
__device__ __half g_wq [(size_t)DN * DK];   // dequantized weight, fp16
__device__ __half g_xh [(size_t)DM * DK];   // x, fp16

// ---------------- PTX helpers (baseline sm_80+ ISA only) ----------------
__device__ __forceinline__ uint32_t smem_u32(const void* p) {
    uint32_t a;
    asm("{ .reg .u64 t; cvta.to.shared.u64 t, %1; cvt.u32.u64 %0, t; }" : "=r"(a) : "l"(p));
    return a;
}
__device__ __forceinline__ uint32_t swz128(uint32_t off) {
    return off ^ ((off >> 3) & 0x70);
}
__device__ __forceinline__ void cp_async16(uint32_t saddr, const void* gaddr) {
    asm volatile("cp.async.cg.shared.global [%0], [%1], 16;" :: "r"(saddr), "l"(gaddr) : "memory");
}
__device__ __forceinline__ void cp_commit() {
    asm volatile("cp.async.commit_group;" ::: "memory");
}
template <int N>
__device__ __forceinline__ void cp_wait() {
    asm volatile("cp.async.wait_group %0;" :: "n"(N) : "memory");
}
__device__ __forceinline__ void ldsm4(uint32_t* r, uint32_t addr) {
    asm volatile("ldmatrix.sync.aligned.m8n8.x4.shared.b16 {%0,%1,%2,%3}, [%4];"
                 : "=r"(r[0]), "=r"(r[1]), "=r"(r[2]), "=r"(r[3]) : "r"(addr));
}
// fp16-accumulate MMA: D,C are f16x2 register pairs.
__device__ __forceinline__ void mma16816_f16(uint32_t* d, const uint32_t* a,
                                             uint32_t b0, uint32_t b1) {
    asm volatile(
        "mma.sync.aligned.m16n8k16.row.col.f16.f16.f16.f16 "
        "{%0,%1}, {%2,%3,%4,%5}, {%6,%7}, {%0,%1};"
        : "+r"(d[0]), "+r"(d[1])
        : "r"(a[0]), "r"(a[1]), "r"(a[2]), "r"(a[3]), "r"(b0), "r"(b1));
}

// ---------------- Kernel 1 (fused prep): W fake-quant->fp16  +  X->fp16 ----------------
#define WBLOCKS ((DN * DK / GROUP) / 8)              // 16384
#define XBLOCKS 4096
#define XSTRIDE (XBLOCKS * 256)                      // float4 stride per iteration

__global__ __launch_bounds__(256) void prep_kernel(const float* __restrict__ w,
                                                   const float* __restrict__ x) {
    const int bx = blockIdx.x;
    if (bx < WBLOCKS) {
        // ---- weight fake-quant ----
        const int warp = threadIdx.x >> 5;
        const int lane = threadIdx.x & 31;
        const long g = (long)bx * 8 + warp;          // group over flattened W

        const float4 v4 = ((const float4*)(w + g * GROUP))[lane];
        float v[4] = {v4.x, v4.y, v4.z, v4.w};

        float mn = fminf(fminf(v[0], v[1]), fminf(v[2], v[3]));
        float mx = fmaxf(fmaxf(v[0], v[1]), fmaxf(v[2], v[3]));
#pragma unroll
        for (int o = 16; o > 0; o >>= 1) {
            mn = fminf(mn, __shfl_xor_sync(0xffffffffu, mn, o));
            mx = fmaxf(mx, __shfl_xor_sync(0xffffffffu, mx, o));
        }
        const float rng = mx - mn;
        const bool pass = rng < EPSQ;
        const float scale = rng * (1.0f / 3.0f);
        const float inv = pass ? 1.0f : (1.0f / scale);

        __half h[4];
#pragma unroll
        for (int i = 0; i < 4; i++) {
            float q = rintf((v[i] - mn) * inv);      // half-even like jnp.round
            q = fminf(fmaxf(q, 0.0f), 3.0f);
            float deq = pass ? v[i] : fmaf(q, scale, mn);
            h[i] = __float2half(deq);
        }
        ((uint2*)(g_wq + g * GROUP))[lane] = *(uint2*)h;
    } else {
        // ---- X convert ----
        const size_t base = (size_t)(bx - WBLOCKS) * 256 + threadIdx.x;
        const float4* __restrict__ xp = (const float4*)x;
#pragma unroll
        for (int i = 0; i < 8; i++) {
            const size_t i4 = base + (size_t)i * XSTRIDE;
            float4 v = xp[i4];
            __half h[4];
            h[0] = __float2half(v.x);
            h[1] = __float2half(v.y);
            h[2] = __float2half(v.z);
            h[3] = __float2half(v.w);
            *(uint2*)&g_xh[i4 * 4] = *(uint2*)h;
        }
    }
}

// ---------------- Kernel 2: fp16-accumulate mma.sync GEMM ----------------
// 128x128 CTA tile, 512 threads (16 warps, 4x4 grid of 32x32 warp tiles).
// fp16 accumulators within each K=128 stage, promoted to fp32 per stage.
// Stage: A0 A1 B0 B1, each 128 rows x 128B = 16KB -> 64KB; NBUF=2 -> 128KB.
#define SUB_BYTES (128 * 128)               // 16KB per 64-col sub-tile
#define SA0 0
#define SB0 (2 * SUB_BYTES)
#define STAGE_BYTES (4 * SUB_BYTES)         // 64KB
#define SM_TOTAL (NBUF * STAGE_BYTES)       // 128KB

__global__ __launch_bounds__(512, 1) void gemm_kernel(
    const float* __restrict__ bias, float* __restrict__ C) {

    extern __shared__ char sm[];
    const uint32_t sbase = smem_u32(sm);

    const int tid = threadIdx.x;
    const int wid = tid >> 5;
    const int lane = tid & 31;
    const int wm = wid & 3;           // 0..3 -> warp rows [wm*32, +32)
    const int wn = wid >> 2;          // 0..3 -> warp cols [wn*32, +32)
    const int bn = blockIdx.x * BN;
    const int bm = blockIdx.y * BM;

    const __half* __restrict__ X = g_xh;
    const __half* __restrict__ W = g_wq;

    // loader mapping: 16B chunks within a 64-col sub-tile; 1024 chunks -> 2/thread
    const int lrow = tid >> 3;            // 0..63, advances by 64 (row&7 invariant)
    const int lchk = tid & 7;
    const uint32_t lso = swz128(lrow * 128 + lchk * 16);
    const size_t lgo = (size_t)lrow * DK + lchk * 8;

    auto load_stage = [&](int s, int buf) {
        const uint32_t st = sbase + buf * STAGE_BYTES;
#pragma unroll
        for (int h = 0; h < 2; h++) {
            const int k0 = s * BKE + h * 64;
#pragma unroll
            for (int it = 0; it < 2; it++) {
                cp_async16(st + SA0 + h * SUB_BYTES + lso + it * 64 * 128,
                           X + (size_t)bm * DK + lgo + (size_t)it * 64 * DK + k0);
                cp_async16(st + SB0 + h * SUB_BYTES + lso + it * 64 * 128,
                           W + (size_t)bn * DK + lgo + (size_t)it * 64 * DK + k0);
            }
        }
        cp_commit();
    };

    // fp32 shadow accumulators: warp tile 32x32 -> 32 outputs/thread
    float accf[2][4][4];                 // [mt][n8][quad]
#pragma unroll
    for (int i = 0; i < 2; i++)
#pragma unroll
        for (int j = 0; j < 4; j++)
#pragma unroll
            for (int c = 0; c < 4; c++) accf[i][j][c] = 0.0f;

    // ldmatrix per-lane base byte offsets (unswizzled, within a sub-tile)
    const uint32_t arow = (uint32_t)(wm * 32 + (lane & 15)) * 128 + (uint32_t)(lane >> 4) * 16;
    const uint32_t brow = (uint32_t)(wn * 32 + (lane & 15)) * 128 + (uint32_t)(lane >> 4) * 16;

    load_stage(0, 0);

    for (int s = 0; s < NSTAGES; s++) {
        cp_wait<0>();                 // stage s fully resident
        __syncthreads();              // all warps done with stage s-1's buffer
        if (s + 1 < NSTAGES)
            load_stage(s + 1, (s + 1) & 1);   // overwrite s-1's buffer

        const uint32_t st = sbase + (s & 1) * STAGE_BYTES;

        // fp16 stage accumulators (f16x2 pairs), zeroed per stage
        uint32_t acch[2][4][2];
#pragma unroll
        for (int i = 0; i < 2; i++)
#pragma unroll
            for (int j = 0; j < 4; j++) { acch[i][j][0] = 0u; acch[i][j][1] = 0u; }

#pragma unroll
        for (int kk = 0; kk < 8; kk++) {
            const int half = kk >> 2;
            const int ksub = kk & 3;
            const uint32_t sA = st + SA0 + half * SUB_BYTES;
            const uint32_t sB = st + SB0 + half * SUB_BYTES;

            uint32_t a[2][4], b[2][4];
#pragma unroll
            for (int nt = 0; nt < 2; nt++)
                ldsm4(b[nt], sB + swz128(brow + nt * 2048 + ksub * 32));
#pragma unroll
            for (int mt = 0; mt < 2; mt++)
                ldsm4(a[mt], sA + swz128(arow + mt * 2048 + ksub * 32));
#pragma unroll
            for (int mt = 0; mt < 2; mt++)
#pragma unroll
                for (int nt = 0; nt < 2; nt++) {
                    mma16816_f16(acch[mt][nt * 2 + 0], a[mt], b[nt][0], b[nt][2]);
                    mma16816_f16(acch[mt][nt * 2 + 1], a[mt], b[nt][1], b[nt][3]);
                }
        }

        // ---- promote stage partials to fp32 shadow ----
#pragma unroll
        for (int mt = 0; mt < 2; mt++)
#pragma unroll
            for (int n8 = 0; n8 < 4; n8++) {
                const float2 lo = __half22float2(*(__half2*)&acch[mt][n8][0]);
                const float2 hi = __half22float2(*(__half2*)&acch[mt][n8][1]);
                accf[mt][n8][0] += lo.x;
                accf[mt][n8][1] += lo.y;
                accf[mt][n8][2] += hi.x;
                accf[mt][n8][3] += hi.y;
            }
        // buffer reuse gated by next iteration's cp_wait + syncthreads
    }

    // ---- epilogue: + bias, float2 stores ----
    const int qr = lane >> 2;           // 0..7
    const int qc = (lane & 3) * 2;      // 0,2,4,6
#pragma unroll
    for (int mt = 0; mt < 2; mt++) {
        const int r0 = bm + wm * 32 + mt * 16 + qr;
#pragma unroll
        for (int n8 = 0; n8 < 4; n8++) {
            const int col = bn + wn * 32 + n8 * 8 + qc;
            const float2 bv = *(const float2*)(bias + col);
            float2 o0, o1;
            o0.x = accf[mt][n8][0] + bv.x;
            o0.y = accf[mt][n8][1] + bv.y;
            o1.x = accf[mt][n8][2] + bv.x;
            o1.y = accf[mt][n8][3] + bv.y;
            *(float2*)(C + (size_t)r0 * DN + col) = o0;
            *(float2*)(C + (size_t)(r0 + 8) * DN + col) = o1;
        }
    }
}

// ---------------------------------------------------------------------------
extern "C" void kernel_launch(void* const* d_in, const int* in_sizes, int n_in,
                              void* d_out, int out_size) {
    const float* x    = (const float*)d_in[0];
    const float* w    = (const float*)d_in[1];
    const float* bias = (const float*)d_in[2];
    float* out = (float*)d_out;

    cudaFuncSetAttribute(gemm_kernel, cudaFuncAttributeMaxDynamicSharedMemorySize, SM_TOTAL);

    prep_kernel<<<WBLOCKS + XBLOCKS, 256>>>(w, x);

    dim3 grid(DN / BN, DM / BM);
    gemm_kernel<<<grid, 512, SM_TOTAL>>>(bias, out);
}

// round 15
// speedup vs baseline: 1.6832x; 1.6832x over previous
#include <cuda_runtime.h>
#include <cuda_fp16.h>
#include <cstdint>

#define DK 4096
#define DN 4096
#define DM 8192
#define GROUP 128
#define EPSQ 1e-8f

#define BM 128
#define BN 256
#define BKE 128                // K elements per stage (two 64-col SW128 sub-tiles)
#define NSTAGES (DK / BKE)     // 32
#define NBUF 2

// ---------------- device scratch (allocation-free rule) ----------------
__device__ __half g_wq [(size_t)DN * DK];   // dequantized weight, fp16
__device__ __half g_xh [(size_t)DM * DK];   // x, fp16

// ---------------- PTX helpers (baseline sm_80+ ISA only) ----------------
__device__ __forceinline__ uint32_t smem_u32(const void* p) {
    uint32_t a;
    asm("{ .reg .u64 t; cvta.to.shared.u64 t, %1; cvt.u32.u64 %0, t; }" : "=r"(a) : "l"(p));
    return a;
}
__device__ __forceinline__ uint32_t swz128(uint32_t off) {
    return off ^ ((off >> 3) & 0x70);
}
__device__ __forceinline__ void cp_async16(uint32_t saddr, const void* gaddr) {
    asm volatile("cp.async.cg.shared.global [%0], [%1], 16;" :: "r"(saddr), "l"(gaddr) : "memory");
}
__device__ __forceinline__ void cp_commit() {
    asm volatile("cp.async.commit_group;" ::: "memory");
}
template <int N>
__device__ __forceinline__ void cp_wait() {
    asm volatile("cp.async.wait_group %0;" :: "n"(N) : "memory");
}
__device__ __forceinline__ void ldsm4(uint32_t* r, uint32_t addr) {
    asm volatile("ldmatrix.sync.aligned.m8n8.x4.shared.b16 {%0,%1,%2,%3}, [%4];"
                 : "=r"(r[0]), "=r"(r[1]), "=r"(r[2]), "=r"(r[3]) : "r"(addr));
}
__device__ __forceinline__ void mma16816(float* d, const uint32_t* a, uint32_t b0, uint32_t b1) {
    asm volatile(
        "mma.sync.aligned.m16n8k16.row.col.f32.f16.f16.f32 "
        "{%0,%1,%2,%3}, {%4,%5,%6,%7}, {%8,%9}, {%0,%1,%2,%3};"
        : "+f"(d[0]), "+f"(d[1]), "+f"(d[2]), "+f"(d[3])
        : "r"(a[0]), "r"(a[1]), "r"(a[2]), "r"(a[3]), "r"(b0), "r"(b1));
}

// ---------------- Kernel 1 (fused prep): W fake-quant->fp16  +  X->fp16 ----------------
// W blocks: 8 groups per block (1 warp each).
// X blocks: each converts a CONTIGUOUS 8192-element (32KB fp32) span.
#define WBLOCKS ((DN * DK / GROUP) / 8)              // 16384
#define XBLOCKS (((size_t)DM * DK) / 8192)           // 4096

__global__ __launch_bounds__(256) void prep_kernel(const float* __restrict__ w,
                                                   const float* __restrict__ x) {
    const int bx = blockIdx.x;
    if (bx < WBLOCKS) {
        // ---- weight fake-quant ----
        const int warp = threadIdx.x >> 5;
        const int lane = threadIdx.x & 31;
        const long g = (long)bx * 8 + warp;          // group over flattened W

        const float4 v4 = ((const float4*)(w + g * GROUP))[lane];
        float v[4] = {v4.x, v4.y, v4.z, v4.w};

        float mn = fminf(fminf(v[0], v[1]), fminf(v[2], v[3]));
        float mx = fmaxf(fmaxf(v[0], v[1]), fmaxf(v[2], v[3]));
#pragma unroll
        for (int o = 16; o > 0; o >>= 1) {
            mn = fminf(mn, __shfl_xor_sync(0xffffffffu, mn, o));
            mx = fmaxf(mx, __shfl_xor_sync(0xffffffffu, mx, o));
        }
        const float rng = mx - mn;
        const bool pass = rng < EPSQ;
        const float scale = rng * (1.0f / 3.0f);
        const float inv = pass ? 1.0f : (1.0f / scale);

        __half h[4];
#pragma unroll
        for (int i = 0; i < 4; i++) {
            float q = rintf((v[i] - mn) * inv);      // half-even like jnp.round
            q = fminf(fmaxf(q, 0.0f), 3.0f);
            float deq = pass ? v[i] : fmaf(q, scale, mn);
            h[i] = __float2half(deq);
        }
        ((uint2*)(g_wq + g * GROUP))[lane] = *(uint2*)h;
    } else {
        // ---- X convert: contiguous 8192 floats per block (2048 float4, 8/thread) ----
        const size_t blk0 = (size_t)(bx - WBLOCKS) * 2048;
        const float4* __restrict__ xp = (const float4*)x;
#pragma unroll
        for (int i = 0; i < 8; i++) {
            const size_t i4 = blk0 + (size_t)i * 256 + threadIdx.x;
            float4 v = xp[i4];
            __half h[4];
            h[0] = __float2half(v.x);
            h[1] = __float2half(v.y);
            h[2] = __float2half(v.z);
            h[3] = __float2half(v.w);
            *(uint2*)&g_xh[i4 * 4] = *(uint2*)h;
        }
    }
}

// ---------------- Kernel 2: single-pass fp16 mma.sync GEMM (R12 config) ----------------
// 128x256 CTA tile, 512 threads (16 warps, 4x4 grid of 32x64 warp tiles).
// BKE=128: each stage holds TWO 64-col SW128 sub-tiles per operand.
// Stage: A0(16K) A1(16K) B0(32K) B1(32K) = 96KB; NBUF=2 -> 192KB smem.
#define A_HALF (128 * 128)                  // 16KB: 128 rows x 128B
#define B_HALF (256 * 128)                  // 32KB
#define SA0 0
#define SB0 (2 * A_HALF)
#define STAGE_BYTES (2 * A_HALF + 2 * B_HALF)   // 96KB
#define SM_TOTAL (NBUF * STAGE_BYTES)           // 192KB

__global__ __launch_bounds__(512, 1) void gemm_kernel(
    const float* __restrict__ bias, float* __restrict__ C) {

    extern __shared__ char sm[];
    const uint32_t sbase = smem_u32(sm);

    const int tid = threadIdx.x;
    const int wid = tid >> 5;
    const int lane = tid & 31;
    const int wm = wid & 3;           // 0..3 -> warp rows [wm*32, +32)
    const int wn = wid >> 2;          // 0..3 -> warp cols [wn*64, +64)
    const int bn = blockIdx.x * BN;
    const int bm = blockIdx.y * BM;

    const __half* __restrict__ X = g_xh;
    const __half* __restrict__ W = g_wq;

    // loader mapping: 16B chunks within a 64-col sub-tile; row=idx>>3, chunk=idx&7
    const int lrow = tid >> 3;            // 0..63, advances by 64 (row&7 invariant)
    const int lchk = tid & 7;
    const uint32_t lso = swz128(lrow * 128 + lchk * 16);
    const size_t lgo = (size_t)lrow * DK + lchk * 8;

    auto load_stage = [&](int s, int buf) {
        const uint32_t st = sbase + buf * STAGE_BYTES;
#pragma unroll
        for (int h = 0; h < 2; h++) {
            const int k0 = s * BKE + h * 64;
            // A sub-tile: 128 rows -> 1024 chunks -> 2 per thread
#pragma unroll
            for (int it = 0; it < 2; it++) {
                cp_async16(st + SA0 + h * A_HALF + lso + it * 64 * 128,
                           X + (size_t)bm * DK + lgo + (size_t)it * 64 * DK + k0);
            }
            // B sub-tile: 256 rows -> 2048 chunks -> 4 per thread
#pragma unroll
            for (int it = 0; it < 4; it++) {
                cp_async16(st + SB0 + h * B_HALF + lso + it * 64 * 128,
                           W + (size_t)bn * DK + lgo + (size_t)it * 64 * DK + k0);
            }
        }
        cp_commit();
    };

    float accb[2][8][4];
#pragma unroll
    for (int i = 0; i < 2; i++)
#pragma unroll
        for (int j = 0; j < 8; j++)
#pragma unroll
            for (int c = 0; c < 4; c++) accb[i][j][c] = 0.0f;

    // ldmatrix per-lane base byte offsets (unswizzled, within a sub-tile)
    const uint32_t arow = (uint32_t)(wm * 32 + (lane & 15)) * 128 + (uint32_t)(lane >> 4) * 16;
    const uint32_t brow = (uint32_t)(wn * 64 + (lane & 15)) * 128 + (uint32_t)(lane >> 4) * 16;

    load_stage(0, 0);

    for (int s = 0; s < NSTAGES; s++) {
        cp_wait<0>();                 // stage s fully resident
        __syncthreads();              // all warps done with stage s-1's buffer
        if (s + 1 < NSTAGES)
            load_stage(s + 1, (s + 1) & 1);   // overwrite s-1's buffer

        const uint32_t st = sbase + (s & 1) * STAGE_BYTES;

#pragma unroll
        for (int kk = 0; kk < 8; kk++) {
            const int half = kk >> 2;
            const int ksub = kk & 3;
            const uint32_t sA = st + SA0 + half * A_HALF;
            const uint32_t sB = st + SB0 + half * B_HALF;

            uint32_t a[2][4], b[4][4];
#pragma unroll
            for (int nt = 0; nt < 4; nt++)
                ldsm4(b[nt], sB + swz128(brow + nt * 2048 + ksub * 32));
#pragma unroll
            for (int mt = 0; mt < 2; mt++)
                ldsm4(a[mt], sA + swz128(arow + mt * 2048 + ksub * 32));
#pragma unroll
            for (int mt = 0; mt < 2; mt++)
#pragma unroll
                for (int nt = 0; nt < 4; nt++) {
                    mma16816(accb[mt][nt * 2 + 0], a[mt], b[nt][0], b[nt][2]);
                    mma16816(accb[mt][nt * 2 + 1], a[mt], b[nt][1], b[nt][3]);
                }
        }
        // buffer reuse gated by next iteration's cp_wait + syncthreads
    }

    // ---- epilogue: + bias, float2 stores ----
    const int qr = lane >> 2;           // 0..7
    const int qc = (lane & 3) * 2;      // 0,2,4,6
#pragma unroll
    for (int mt = 0; mt < 2; mt++) {
        const int r0 = bm + wm * 32 + mt * 16 + qr;
#pragma unroll
        for (int n8 = 0; n8 < 8; n8++) {
            const int col = bn + wn * 64 + n8 * 8 + qc;
            const float2 bv = *(const float2*)(bias + col);
            float2 o0, o1;
            o0.x = accb[mt][n8][0] + bv.x;
            o0.y = accb[mt][n8][1] + bv.y;
            o1.x = accb[mt][n8][2] + bv.x;
            o1.y = accb[mt][n8][3] + bv.y;
            *(float2*)(C + (size_t)r0 * DN + col) = o0;
            *(float2*)(C + (size_t)(r0 + 8) * DN + col) = o1;
        }
    }
}

// ---------------------------------------------------------------------------
extern "C" void kernel_launch(void* const* d_in, const int* in_sizes, int n_in,
                              void* d_out, int out_size) {
    const float* x    = (const float*)d_in[0];
    const float* w    = (const float*)d_in[1];
    const float* bias = (const float*)d_in[2];
    float* out = (float*)d_out;

    cudaFuncSetAttribute(gemm_kernel, cudaFuncAttributeMaxDynamicSharedMemorySize, SM_TOTAL);

    prep_kernel<<<WBLOCKS + (int)XBLOCKS, 256>>>(w, x);

    dim3 grid(DN / BN, DM / BM);
    gemm_kernel<<<grid, 512, SM_TOTAL>>>(bias, out);
}

// round 17
// speedup vs baseline: 1.6857x; 1.0015x over previous
#include <cuda_runtime.h>
#include <cuda_fp16.h>
#include <cstdint>

#define DK 4096
#define DN 4096
#define DM 8192
#define GROUP 128
#define EPSQ 1e-8f

#define BM 128
#define BN 256
#define BKE 128                // K elements per stage (two 64-col SW128 sub-tiles)
#define NSTAGES (DK / BKE)     // 32
#define NBUF 2

// ---------------- device scratch (allocation-free rule) ----------------
__device__ __half g_wq [(size_t)DN * DK];   // dequantized weight, fp16
__device__ __half g_xh [(size_t)DM * DK];   // x, fp16

// ---------------- PTX helpers (baseline sm_80+ ISA only) ----------------
__device__ __forceinline__ uint32_t smem_u32(const void* p) {
    uint32_t a;
    asm("{ .reg .u64 t; cvta.to.shared.u64 t, %1; cvt.u32.u64 %0, t; }" : "=r"(a) : "l"(p));
    return a;
}
__device__ __forceinline__ uint32_t swz128(uint32_t off) {
    return off ^ ((off >> 3) & 0x70);
}
__device__ __forceinline__ void cp_async16(uint32_t saddr, const void* gaddr) {
    asm volatile("cp.async.cg.shared.global [%0], [%1], 16;" :: "r"(saddr), "l"(gaddr) : "memory");
}
__device__ __forceinline__ void cp_commit() {
    asm volatile("cp.async.commit_group;" ::: "memory");
}
template <int N>
__device__ __forceinline__ void cp_wait() {
    asm volatile("cp.async.wait_group %0;" :: "n"(N) : "memory");
}
__device__ __forceinline__ void ldsm4(uint32_t* r, uint32_t addr) {
    asm volatile("ldmatrix.sync.aligned.m8n8.x4.shared.b16 {%0,%1,%2,%3}, [%4];"
                 : "=r"(r[0]), "=r"(r[1]), "=r"(r[2]), "=r"(r[3]) : "r"(addr));
}
__device__ __forceinline__ void mma16816(float* d, const uint32_t* a, uint32_t b0, uint32_t b1) {
    asm volatile(
        "mma.sync.aligned.m16n8k16.row.col.f32.f16.f16.f32 "
        "{%0,%1,%2,%3}, {%4,%5,%6,%7}, {%8,%9}, {%0,%1,%2,%3};"
        : "+f"(d[0]), "+f"(d[1]), "+f"(d[2]), "+f"(d[3])
        : "r"(a[0]), "r"(a[1]), "r"(a[2]), "r"(a[3]), "r"(b0), "r"(b1));
}

// ---------------- Kernel 1 (fused prep): W fake-quant->fp16  +  X->fp16 ----------------
// W blocks: 8 groups per block (1 warp each), one LDG.128 per thread.
// X blocks: contiguous 8192-element span; all 8 LDG.128 front-batched (MLP=8),
// then all converts+stores — raises MLP_eff to hide DRAM/TLB latency.
#define WBLOCKS ((DN * DK / GROUP) / 8)              // 16384
#define XBLOCKS (((size_t)DM * DK) / 8192)           // 4096

__global__ __launch_bounds__(256) void prep_kernel(const float* __restrict__ w,
                                                   const float* __restrict__ x) {
    const int bx = blockIdx.x;
    if (bx < WBLOCKS) {
        // ---- weight fake-quant ----
        const int warp = threadIdx.x >> 5;
        const int lane = threadIdx.x & 31;
        const long g = (long)bx * 8 + warp;          // group over flattened W

        const float4 v4 = ((const float4*)(w + g * GROUP))[lane];
        float v[4] = {v4.x, v4.y, v4.z, v4.w};

        float mn = fminf(fminf(v[0], v[1]), fminf(v[2], v[3]));
        float mx = fmaxf(fmaxf(v[0], v[1]), fmaxf(v[2], v[3]));
#pragma unroll
        for (int o = 16; o > 0; o >>= 1) {
            mn = fminf(mn, __shfl_xor_sync(0xffffffffu, mn, o));
            mx = fmaxf(mx, __shfl_xor_sync(0xffffffffu, mx, o));
        }
        const float rng = mx - mn;
        const bool pass = rng < EPSQ;
        const float scale = rng * (1.0f / 3.0f);
        const float inv = pass ? 1.0f : (1.0f / scale);

        __half h[4];
#pragma unroll
        for (int i = 0; i < 4; i++) {
            float q = rintf((v[i] - mn) * inv);      // half-even like jnp.round
            q = fminf(fmaxf(q, 0.0f), 3.0f);
            float deq = pass ? v[i] : fmaf(q, scale, mn);
            h[i] = __float2half(deq);
        }
        ((uint2*)(g_wq + g * GROUP))[lane] = *(uint2*)h;
    } else {
        // ---- X convert: front-batched loads (MLP=8), then converts+stores ----
        const size_t blk0 = (size_t)(bx - WBLOCKS) * 2048;
        const float4* __restrict__ xp = (const float4*)x;
        float4 v[8];
#pragma unroll
        for (int i = 0; i < 8; i++)
            v[i] = xp[blk0 + (size_t)i * 256 + threadIdx.x];
#pragma unroll
        for (int i = 0; i < 8; i++) {
            const size_t i4 = blk0 + (size_t)i * 256 + threadIdx.x;
            __half h[4];
            h[0] = __float2half(v[i].x);
            h[1] = __float2half(v[i].y);
            h[2] = __float2half(v[i].z);
            h[3] = __float2half(v[i].w);
            *(uint2*)&g_xh[i4 * 4] = *(uint2*)h;
        }
    }
}

// ---------------- Kernel 2: single-pass fp16 mma.sync GEMM (R12 config, floor) ----------------
// 128x256 CTA tile, 512 threads (16 warps, 4x4 grid of 32x64 warp tiles).
// BKE=128: each stage holds TWO 64-col SW128 sub-tiles per operand.
// Stage: A0(16K) A1(16K) B0(32K) B1(32K) = 96KB; NBUF=2 -> 192KB smem.
#define A_HALF (128 * 128)                  // 16KB: 128 rows x 128B
#define B_HALF (256 * 128)                  // 32KB
#define SA0 0
#define SB0 (2 * A_HALF)
#define STAGE_BYTES (2 * A_HALF + 2 * B_HALF)   // 96KB
#define SM_TOTAL (NBUF * STAGE_BYTES)           // 192KB

__global__ __launch_bounds__(512, 1) void gemm_kernel(
    const float* __restrict__ bias, float* __restrict__ C) {

    extern __shared__ char sm[];
    const uint32_t sbase = smem_u32(sm);

    const int tid = threadIdx.x;
    const int wid = tid >> 5;
    const int lane = tid & 31;
    const int wm = wid & 3;           // 0..3 -> warp rows [wm*32, +32)
    const int wn = wid >> 2;          // 0..3 -> warp cols [wn*64, +64)
    const int bn = blockIdx.x * BN;
    const int bm = blockIdx.y * BM;

    const __half* __restrict__ X = g_xh;
    const __half* __restrict__ W = g_wq;

    // loader mapping: 16B chunks within a 64-col sub-tile; row=idx>>3, chunk=idx&7
    const int lrow = tid >> 3;            // 0..63, advances by 64 (row&7 invariant)
    const int lchk = tid & 7;
    const uint32_t lso = swz128(lrow * 128 + lchk * 16);
    const size_t lgo = (size_t)lrow * DK + lchk * 8;

    auto load_stage = [&](int s, int buf) {
        const uint32_t st = sbase + buf * STAGE_BYTES;
#pragma unroll
        for (int h = 0; h < 2; h++) {
            const int k0 = s * BKE + h * 64;
            // A sub-tile: 128 rows -> 1024 chunks -> 2 per thread
#pragma unroll
            for (int it = 0; it < 2; it++) {
                cp_async16(st + SA0 + h * A_HALF + lso + it * 64 * 128,
                           X + (size_t)bm * DK + lgo + (size_t)it * 64 * DK + k0);
            }
            // B sub-tile: 256 rows -> 2048 chunks -> 4 per thread
#pragma unroll
            for (int it = 0; it < 4; it++) {
                cp_async16(st + SB0 + h * B_HALF + lso + it * 64 * 128,
                           W + (size_t)bn * DK + lgo + (size_t)it * 64 * DK + k0);
            }
        }
        cp_commit();
    };

    float accb[2][8][4];
#pragma unroll
    for (int i = 0; i < 2; i++)
#pragma unroll
        for (int j = 0; j < 8; j++)
#pragma unroll
            for (int c = 0; c < 4; c++) accb[i][j][c] = 0.0f;

    // ldmatrix per-lane base byte offsets (unswizzled, within a sub-tile)
    const uint32_t arow = (uint32_t)(wm * 32 + (lane & 15)) * 128 + (uint32_t)(lane >> 4) * 16;
    const uint32_t brow = (uint32_t)(wn * 64 + (lane & 15)) * 128 + (uint32_t)(lane >> 4) * 16;

    load_stage(0, 0);

    for (int s = 0; s < NSTAGES; s++) {
        cp_wait<0>();                 // stage s fully resident
        __syncthreads();              // all warps done with stage s-1's buffer
        if (s + 1 < NSTAGES)
            load_stage(s + 1, (s + 1) & 1);   // overwrite s-1's buffer

        const uint32_t st = sbase + (s & 1) * STAGE_BYTES;

#pragma unroll
        for (int kk = 0; kk < 8; kk++) {
            const int half = kk >> 2;
            const int ksub = kk & 3;
            const uint32_t sA = st + SA0 + half * A_HALF;
            const uint32_t sB = st + SB0 + half * B_HALF;

            uint32_t a[2][4], b[4][4];
#pragma unroll
            for (int nt = 0; nt < 4; nt++)
                ldsm4(b[nt], sB + swz128(brow + nt * 2048 + ksub * 32));
#pragma unroll
            for (int mt = 0; mt < 2; mt++)
                ldsm4(a[mt], sA + swz128(arow + mt * 2048 + ksub * 32));
#pragma unroll
            for (int mt = 0; mt < 2; mt++)
#pragma unroll
                for (int nt = 0; nt < 4; nt++) {
                    mma16816(accb[mt][nt * 2 + 0], a[mt], b[nt][0], b[nt][2]);
                    mma16816(accb[mt][nt * 2 + 1], a[mt], b[nt][1], b[nt][3]);
                }
        }
        // buffer reuse gated by next iteration's cp_wait + syncthreads
    }

    // ---- epilogue: + bias, float2 stores ----
    const int qr = lane >> 2;           // 0..7
    const int qc = (lane & 3) * 2;      // 0,2,4,6
#pragma unroll
    for (int mt = 0; mt < 2; mt++) {
        const int r0 = bm + wm * 32 + mt * 16 + qr;
#pragma unroll
        for (int n8 = 0; n8 < 8; n8++) {
            const int col = bn + wn * 64 + n8 * 8 + qc;
            const float2 bv = *(const float2*)(bias + col);
            float2 o0, o1;
            o0.x = accb[mt][n8][0] + bv.x;
            o0.y = accb[mt][n8][1] + bv.y;
            o1.x = accb[mt][n8][2] + bv.x;
            o1.y = accb[mt][n8][3] + bv.y;
            *(float2*)(C + (size_t)r0 * DN + col) = o0;
            *(float2*)(C + (size_t)(r0 + 8) * DN + col) = o1;
        }
    }
}

// ---------------------------------------------------------------------------
extern "C" void kernel_launch(void* const* d_in, const int* in_sizes, int n_in,
                              void* d_out, int out_size) {
    const float* x    = (const float*)d_in[0];
    const float* w    = (const float*)d_in[1];
    const float* bias = (const float*)d_in[2];
    float* out = (float*)d_out;

    cudaFuncSetAttribute(gemm_kernel, cudaFuncAttributeMaxDynamicSharedMemorySize, SM_TOTAL);

    prep_kernel<<<WBLOCKS + (int)XBLOCKS, 256>>>(w, x);

    dim3 grid(DN / BN, DM / BM);
    gemm_kernel<<<grid, 512, SM_TOTAL>>>(bias, out);
}